// round 3
// baseline (speedup 1.0000x reference)
#include <cuda_runtime.h>
#include <cuda_bf16.h>
#include <stdint.h>

#define NUM_SEGMENTS 4480
#define ATOM_DIM 64
#define BOND_DIM 16
#define N_EDGES 65536
#define NCOLS 1088   // 16*64 kernel-projected cols + 64 bias cols

// Scratch (device globals — no allocation allowed)
__device__ float g_Y[(size_t)NUM_SEGMENTS * NCOLS];
__device__ int   g_count[NUM_SEGMENTS];
__device__ int   g_offset[NUM_SEGMENTS + 1];
__device__ int   g_cursor[NUM_SEGMENTS];
__device__ int   g_eid[N_EDGES];

// ---------------------------------------------------------------------------
// Phase 1: Y = atom_feat (4480x64) @ W (64x1088)
//   W[j][k*64+i]   = kernel[k*4096 + i*64 + j]
//   W[j][1024 + i] = bias[i*64 + j]
// ---------------------------------------------------------------------------
__global__ void __launch_bounds__(256, 6)
proj_kernel(const float* __restrict__ atom,
            const float* __restrict__ kern,
            const float* __restrict__ bias)
{
    __shared__ float As[64][65];
    __shared__ float Ws[64][65];

    const int a0 = blockIdx.x * 64;
    const int c0 = blockIdx.y * 64;
    const int tid = threadIdx.x;

    #pragma unroll
    for (int t = 0; t < 16; t++) {
        int idx = tid + t * 256;
        int r = idx >> 6, j = idx & 63;
        As[r][j] = atom[(a0 + r) * 64 + j];
    }
    #pragma unroll
    for (int t = 0; t < 16; t++) {
        int idx = tid + t * 256;
        int j = idx & 63, cc = idx >> 6;
        int c = c0 + cc;
        float w;
        if (c < 1024) {
            int k = c >> 6, i = c & 63;
            w = kern[k * 4096 + i * 64 + j];
        } else {
            w = bias[(c - 1024) * 64 + j];
        }
        Ws[j][cc] = w;
    }
    __syncthreads();

    const int tx = tid & 15;
    const int ty = tid >> 4;
    float acc[4][4] = {};

    #pragma unroll
    for (int k = 0; k < 64; k++) {
        float av[4], wv[4];
        #pragma unroll
        for (int r = 0; r < 4; r++) av[r] = As[ty * 4 + r][k];
        #pragma unroll
        for (int c = 0; c < 4; c++) wv[c] = Ws[k][tx * 4 + c];
        #pragma unroll
        for (int r = 0; r < 4; r++)
            #pragma unroll
            for (int c = 0; c < 4; c++)
                acc[r][c] = fmaf(av[r], wv[c], acc[r][c]);
    }

    #pragma unroll
    for (int r = 0; r < 4; r++) {
        size_t row = (size_t)(a0 + ty * 4 + r);
        #pragma unroll
        for (int c = 0; c < 4; c++)
            g_Y[row * NCOLS + (c0 + tx * 4 + c)] = acc[r][c];
    }
}

// ---------------------------------------------------------------------------
// Binning by src (pair[:,1])
// ---------------------------------------------------------------------------
__global__ void zero_counts_kernel()
{
    int i = blockIdx.x * blockDim.x + threadIdx.x;
    if (i < NUM_SEGMENTS) g_count[i] = 0;
}

__global__ void hist_kernel(const int* __restrict__ pair)
{
    int e = blockIdx.x * blockDim.x + threadIdx.x;
    if (e < N_EDGES) atomicAdd(&g_count[pair[2 * e + 1]], 1);
}

// Single-block exclusive scan of g_count (4480) -> g_offset, g_cursor
__global__ void __launch_bounds__(1024)
scan_kernel()
{
    __shared__ int chunk[1024];
    const int C = 5;            // 1024*5 = 5120 >= 4480
    int t = threadIdx.x;
    int base = t * C;

    int s = 0;
    #pragma unroll
    for (int j = 0; j < C; j++) {
        int idx = base + j;
        if (idx < NUM_SEGMENTS) s += g_count[idx];
    }
    chunk[t] = s;
    __syncthreads();

    // Hillis-Steele inclusive scan over 1024 chunk sums
    for (int off = 1; off < 1024; off <<= 1) {
        int v = (t >= off) ? chunk[t - off] : 0;
        __syncthreads();
        chunk[t] += v;
        __syncthreads();
    }

    int run = (t == 0) ? 0 : chunk[t - 1];
    #pragma unroll
    for (int j = 0; j < C; j++) {
        int idx = base + j;
        if (idx < NUM_SEGMENTS) {
            g_offset[idx] = run;
            g_cursor[idx] = run;
            run += g_count[idx];
        }
    }
    if (t == 1023) g_offset[NUM_SEGMENTS] = run;
}

__global__ void scatter_kernel(const int* __restrict__ pair)
{
    int e = blockIdx.x * blockDim.x + threadIdx.x;
    if (e < N_EDGES) {
        int src = pair[2 * e + 1];
        int pos = atomicAdd(&g_cursor[src], 1);
        g_eid[pos] = e;
    }
}

// ---------------------------------------------------------------------------
// Phase 2: one warp per src atom. Y[src] loaded to regs once; stream edges.
//   msg_e[i] = Y[src][1024+i] + sum_k b_e[k] * Y[src][k*64+i]
// ---------------------------------------------------------------------------
__global__ void __launch_bounds__(256)
gather_edge_kernel(const float* __restrict__ bond,
                   const int* __restrict__ pair,
                   float* __restrict__ out)
{
    int a = blockIdx.x * 8 + (threadIdx.x >> 5);
    if (a >= NUM_SEGMENTS) return;
    const int lane = threadIdx.x & 31;

    const int beg = g_offset[a];
    const int end = g_offset[a + 1];
    if (beg == end) return;

    const float* __restrict__ y = g_Y + (size_t)a * NCOLS;

    float yk0[16], yk1[16];
    #pragma unroll
    for (int k = 0; k < 16; k++) {
        yk0[k] = y[k * 64 + lane];
        yk1[k] = y[k * 64 + 32 + lane];
    }
    const float b0 = y[1024 + lane];
    const float b1 = y[1024 + 32 + lane];

    for (int j = beg; j < end; j++) {
        int eid = g_eid[j];
        int dst = pair[2 * eid];

        const float4* __restrict__ bp =
            (const float4*)(bond + (size_t)eid * 16);
        float4 q0 = __ldg(bp + 0);
        float4 q1 = __ldg(bp + 1);
        float4 q2 = __ldg(bp + 2);
        float4 q3 = __ldg(bp + 3);

        float m0 = b0, m1 = b1;
        m0 = fmaf(q0.x, yk0[0],  m0);  m1 = fmaf(q0.x, yk1[0],  m1);
        m0 = fmaf(q0.y, yk0[1],  m0);  m1 = fmaf(q0.y, yk1[1],  m1);
        m0 = fmaf(q0.z, yk0[2],  m0);  m1 = fmaf(q0.z, yk1[2],  m1);
        m0 = fmaf(q0.w, yk0[3],  m0);  m1 = fmaf(q0.w, yk1[3],  m1);
        m0 = fmaf(q1.x, yk0[4],  m0);  m1 = fmaf(q1.x, yk1[4],  m1);
        m0 = fmaf(q1.y, yk0[5],  m0);  m1 = fmaf(q1.y, yk1[5],  m1);
        m0 = fmaf(q1.z, yk0[6],  m0);  m1 = fmaf(q1.z, yk1[6],  m1);
        m0 = fmaf(q1.w, yk0[7],  m0);  m1 = fmaf(q1.w, yk1[7],  m1);
        m0 = fmaf(q2.x, yk0[8],  m0);  m1 = fmaf(q2.x, yk1[8],  m1);
        m0 = fmaf(q2.y, yk0[9],  m0);  m1 = fmaf(q2.y, yk1[9],  m1);
        m0 = fmaf(q2.z, yk0[10], m0);  m1 = fmaf(q2.z, yk1[10], m1);
        m0 = fmaf(q2.w, yk0[11], m0);  m1 = fmaf(q2.w, yk1[11], m1);
        m0 = fmaf(q3.x, yk0[12], m0);  m1 = fmaf(q3.x, yk1[12], m1);
        m0 = fmaf(q3.y, yk0[13], m0);  m1 = fmaf(q3.y, yk1[13], m1);
        m0 = fmaf(q3.z, yk0[14], m0);  m1 = fmaf(q3.z, yk1[14], m1);
        m0 = fmaf(q3.w, yk0[15], m0);  m1 = fmaf(q3.w, yk1[15], m1);

        atomicAdd(&out[(size_t)dst * 64 + lane],      m0);
        atomicAdd(&out[(size_t)dst * 64 + 32 + lane], m1);
    }
}

extern "C" void kernel_launch(void* const* d_in, const int* in_sizes, int n_in,
                              void* d_out, int out_size)
{
    const float* atom = (const float*)d_in[0];      // [4480, 64]
    const float* bond = (const float*)d_in[1];      // [65536, 16]
    const int*   pair = (const int*)d_in[2];        // [65536, 2] int32
    const float* kern = (const float*)d_in[3];      // [16, 4096]
    const float* bias = (const float*)d_in[4];      // [4096]
    float*       out  = (float*)d_out;              // [4480, 64]

    (void)in_sizes; (void)n_in;

    cudaMemsetAsync(out, 0, (size_t)out_size * sizeof(float), 0);

    zero_counts_kernel<<<(NUM_SEGMENTS + 255) / 256, 256>>>();
    hist_kernel<<<N_EDGES / 256, 256>>>(pair);
    scan_kernel<<<1, 1024>>>();
    scatter_kernel<<<N_EDGES / 256, 256>>>(pair);

    dim3 grid1(NUM_SEGMENTS / 64, NCOLS / 64);  // (70, 17)
    proj_kernel<<<grid1, 256>>>(atom, kern, bias);

    gather_edge_kernel<<<(NUM_SEGMENTS + 7) / 8, 256>>>(bond, pair, out);
}

// round 4
// speedup vs baseline: 1.3861x; 1.3861x over previous
#include <cuda_runtime.h>
#include <cuda_fp16.h>
#include <stdint.h>

#define NUM_SEGMENTS 4480
#define ATOM_DIM 64
#define BOND_DIM 16
#define N_EDGES 65536
#define NCOLS 1088   // 16*64 kernel-projected cols + 64 bias cols

// Scratch: per-atom projected features in fp16 (halves L2 traffic in phase 2).
// Y[a][c]: c = k*64+i for c<1024 (kernel proj), c = 1024+i (bias proj).
__device__ __half g_Yh[(size_t)NUM_SEGMENTS * NCOLS];

// ---------------------------------------------------------------------------
// Phase 1: Y = atom_feat (4480x64) @ W (64x1088), output fp16.
//   W[j][k*64+i]   = kernel[k*4096 + i*64 + j]
//   W[j][1024 + i] = bias[i*64 + j]
// Also zeroes `out` (blockIdx.y == 0 blocks) so no separate memset launch.
// ---------------------------------------------------------------------------
__global__ void __launch_bounds__(256, 6)
proj_kernel(const float* __restrict__ atom,
            const float* __restrict__ kern,
            const float* __restrict__ bias,
            float* __restrict__ out)
{
    __shared__ float As[64][65];
    __shared__ float Ws[64][65];

    const int a0 = blockIdx.x * 64;   // 70 blocks
    const int c0 = blockIdx.y * 64;   // 17 blocks
    const int tid = threadIdx.x;

    // Fold output zeroing into the y==0 slice of the grid (out rows a0..a0+63)
    if (blockIdx.y == 0) {
        float4* oz = (float4*)(out + (size_t)a0 * 64);
        // 64 rows * 64 cols = 4096 floats = 1024 float4; 256 threads * 4
        #pragma unroll
        for (int t = 0; t < 4; t++)
            oz[tid + t * 256] = make_float4(0.f, 0.f, 0.f, 0.f);
    }

    #pragma unroll
    for (int t = 0; t < 16; t++) {
        int idx = tid + t * 256;
        int r = idx >> 6, j = idx & 63;
        As[r][j] = atom[(a0 + r) * 64 + j];
    }
    #pragma unroll
    for (int t = 0; t < 16; t++) {
        int idx = tid + t * 256;
        int j = idx & 63, cc = idx >> 6;
        int c = c0 + cc;
        float w;
        if (c < 1024) {
            int k = c >> 6, i = c & 63;
            w = kern[k * 4096 + i * 64 + j];
        } else {
            w = bias[(c - 1024) * 64 + j];
        }
        Ws[j][cc] = w;
    }
    __syncthreads();

    const int tx = tid & 15;
    const int ty = tid >> 4;
    float acc[4][4] = {};

    #pragma unroll
    for (int k = 0; k < 64; k++) {
        float av[4], wv[4];
        #pragma unroll
        for (int r = 0; r < 4; r++) av[r] = As[ty * 4 + r][k];
        #pragma unroll
        for (int c = 0; c < 4; c++) wv[c] = Ws[k][tx * 4 + c];
        #pragma unroll
        for (int r = 0; r < 4; r++)
            #pragma unroll
            for (int c = 0; c < 4; c++)
                acc[r][c] = fmaf(av[r], wv[c], acc[r][c]);
    }

    #pragma unroll
    for (int r = 0; r < 4; r++) {
        size_t row = (size_t)(a0 + ty * 4 + r);
        __half2 h01 = __floats2half2_rn(acc[r][0], acc[r][1]);
        __half2 h23 = __floats2half2_rn(acc[r][2], acc[r][3]);
        __half2* dst = (__half2*)(g_Yh + row * NCOLS + (c0 + tx * 4));
        dst[0] = h01;
        dst[1] = h23;
    }
}

// ---------------------------------------------------------------------------
// Phase 2: half-warp per edge. lanes 0-15 -> edge 2w, lanes 16-31 -> edge 2w+1.
// Lane lid handles output features i = 4*lid .. 4*lid+3.
//   msg[i] = Yh[src][1024+i] + sum_k b_e[k] * Yh[src][k*64+i]
//   atomicAdd(out[dst][i], msg[i])
// ---------------------------------------------------------------------------
__global__ void __launch_bounds__(256)
edge_kernel(const float* __restrict__ bond,
            const int* __restrict__ pair,
            float* __restrict__ out)
{
    const int warp = blockIdx.x * 8 + (threadIdx.x >> 5);
    const int half = (threadIdx.x >> 4) & 1;
    const int lid  = threadIdx.x & 15;
    const int e = warp * 2 + half;          // grid sized so e < N_EDGES always

    const int2 pr = ((const int2*)pair)[e];
    const int dst = pr.x;
    const int src = pr.y;

    // bond row: 16 floats, broadcast to all 16 lanes of the half-warp
    const float4* __restrict__ bp = (const float4*)(bond + (size_t)e * 16);
    const float4 q0 = __ldg(bp + 0);
    const float4 q1 = __ldg(bp + 1);
    const float4 q2 = __ldg(bp + 2);
    const float4 q3 = __ldg(bp + 3);
    const float bk[16] = {q0.x, q0.y, q0.z, q0.w,
                          q1.x, q1.y, q1.z, q1.w,
                          q2.x, q2.y, q2.z, q2.w,
                          q3.x, q3.y, q3.z, q3.w};

    const __half* __restrict__ y = g_Yh + (size_t)src * NCOLS + 4 * lid;

    // bias-projection row
    float m0, m1, m2, m3;
    {
        const uint2 v = *(const uint2*)(y + 1024);
        const __half2 lo = *(const __half2*)&v.x;
        const __half2 hi = *(const __half2*)&v.y;
        const float2 flo = __half22float2(lo);
        const float2 fhi = __half22float2(hi);
        m0 = flo.x; m1 = flo.y; m2 = fhi.x; m3 = fhi.y;
    }

    #pragma unroll
    for (int k = 0; k < 16; k++) {
        const uint2 v = *(const uint2*)(y + k * 64);
        const __half2 lo = *(const __half2*)&v.x;
        const __half2 hi = *(const __half2*)&v.y;
        const float2 flo = __half22float2(lo);
        const float2 fhi = __half22float2(hi);
        const float b = bk[k];
        m0 = fmaf(b, flo.x, m0);
        m1 = fmaf(b, flo.y, m1);
        m2 = fmaf(b, fhi.x, m2);
        m3 = fmaf(b, fhi.y, m3);
    }

    float* o = out + (size_t)dst * 64 + 4 * lid;
    atomicAdd(o + 0, m0);
    atomicAdd(o + 1, m1);
    atomicAdd(o + 2, m2);
    atomicAdd(o + 3, m3);
}

extern "C" void kernel_launch(void* const* d_in, const int* in_sizes, int n_in,
                              void* d_out, int out_size)
{
    const float* atom = (const float*)d_in[0];      // [4480, 64]
    const float* bond = (const float*)d_in[1];      // [65536, 16]
    const int*   pair = (const int*)d_in[2];        // [65536, 2] int32
    const float* kern = (const float*)d_in[3];      // [16, 4096]
    const float* bias = (const float*)d_in[4];      // [4096]
    float*       out  = (float*)d_out;              // [4480, 64]

    (void)in_sizes; (void)n_in; (void)out_size;

    dim3 grid1(NUM_SEGMENTS / 64, NCOLS / 64);  // (70, 17); y==0 blocks zero `out`
    proj_kernel<<<grid1, 256>>>(atom, kern, bias, out);

    // 2 edges per warp, 8 warps per block -> 16 edges per block
    edge_kernel<<<N_EDGES / 16, 256>>>(bond, pair, out);
}

// round 5
// speedup vs baseline: 1.6171x; 1.1667x over previous
#include <cuda_runtime.h>
#include <cuda_fp16.h>
#include <stdint.h>

#define NUM_SEGMENTS 4480
#define ATOM_DIM 64
#define BOND_DIM 16
#define N_EDGES 65536
#define NCOLS 1088   // 16*64 kernel-projected cols + 64 bias cols

// Scratch: per-atom projected features in fp16 (halves L2 traffic in phase 2).
__device__ __half g_Yh[(size_t)NUM_SEGMENTS * NCOLS];

// ---- packed f32x2 helpers (Blackwell FFMA2; bit-identical to 2x scalar fmaf) ----
__device__ __forceinline__ unsigned long long pack2(float lo, float hi) {
    unsigned long long r;
    asm("mov.b64 %0, {%1, %2};" : "=l"(r) : "f"(lo), "f"(hi));
    return r;
}
__device__ __forceinline__ void unpack2(float& lo, float& hi, unsigned long long v) {
    asm("mov.b64 {%0, %1}, %2;" : "=f"(lo), "=f"(hi) : "l"(v));
}
__device__ __forceinline__ void ffma2(unsigned long long& d,
                                      unsigned long long a,
                                      unsigned long long b) {
    asm("fma.rn.f32x2 %0, %1, %2, %0;" : "+l"(d) : "l"(a), "l"(b));
}

// ---------------------------------------------------------------------------
// Phase 1: Y = atom_feat (4480x64) @ W (64x1088), output fp16.
//   W[j][k*64+i]   = kernel[k*4096 + i*64 + j]
//   W[j][1024 + i] = bias[i*64 + j]
// A stored transposed in smem so the k-loop uses two LDS.128 fetches.
// Inner product done with packed fma.rn.f32x2 (row-pair packing).
// Also zeroes `out` (blockIdx.y == 0 blocks).
// ---------------------------------------------------------------------------
__global__ void __launch_bounds__(256, 6)
proj_kernel(const float* __restrict__ atom,
            const float* __restrict__ kern,
            const float* __restrict__ bias,
            float* __restrict__ out)
{
    __shared__ __align__(16) float AsT[64][68];  // AsT[k][row]
    __shared__ __align__(16) float Ws [64][68];  // Ws[k][col]

    const int a0 = blockIdx.x * 64;   // 70 blocks
    const int c0 = blockIdx.y * 64;   // 17 blocks
    const int tid = threadIdx.x;

    if (blockIdx.y == 0) {
        float4* oz = (float4*)(out + (size_t)a0 * 64);
        #pragma unroll
        for (int t = 0; t < 4; t++)
            oz[tid + t * 256] = make_float4(0.f, 0.f, 0.f, 0.f);
    }

    // Load A tile transposed: AsT[j][r] = atom[(a0+r)*64 + j] (gmem coalesced in j)
    #pragma unroll
    for (int t = 0; t < 16; t++) {
        int idx = tid + t * 256;
        int r = idx >> 6, j = idx & 63;
        AsT[j][r] = atom[(a0 + r) * 64 + j];
    }
    // Load W tile: Ws[j][cc] (gmem coalesced in j)
    #pragma unroll
    for (int t = 0; t < 16; t++) {
        int idx = tid + t * 256;
        int j = idx & 63, cc = idx >> 6;
        int c = c0 + cc;
        float w;
        if (c < 1024) {
            int k = c >> 6, i = c & 63;
            w = kern[k * 4096 + i * 64 + j];
        } else {
            w = bias[(c - 1024) * 64 + j];
        }
        Ws[j][cc] = w;
    }
    __syncthreads();

    const int tx = tid & 15;   // col group (4 cols)
    const int ty = tid >> 4;   // row group (4 rows)

    // acc2[rp][c] packs (acc[2rp][c], acc[2rp+1][c]) as f32x2
    unsigned long long acc2[2][4] = {};

    #pragma unroll
    for (int k = 0; k < 64; k++) {
        const float4 aq = *(const float4*)&AsT[k][ty * 4];  // rows ty*4..+3 at col k
        const float4 wq = *(const float4*)&Ws[k][tx * 4];   // cols tx*4..+3 at row k

        const unsigned long long a01 = pack2(aq.x, aq.y);
        const unsigned long long a23 = pack2(aq.z, aq.w);
        const unsigned long long w0 = pack2(wq.x, wq.x);
        const unsigned long long w1 = pack2(wq.y, wq.y);
        const unsigned long long w2 = pack2(wq.z, wq.z);
        const unsigned long long w3 = pack2(wq.w, wq.w);

        ffma2(acc2[0][0], a01, w0);
        ffma2(acc2[0][1], a01, w1);
        ffma2(acc2[0][2], a01, w2);
        ffma2(acc2[0][3], a01, w3);
        ffma2(acc2[1][0], a23, w0);
        ffma2(acc2[1][1], a23, w1);
        ffma2(acc2[1][2], a23, w2);
        ffma2(acc2[1][3], a23, w3);
    }

    #pragma unroll
    for (int rp = 0; rp < 2; rp++) {
        float lo[4], hi[4];
        #pragma unroll
        for (int c = 0; c < 4; c++) unpack2(lo[c], hi[c], acc2[rp][c]);

        size_t row0 = (size_t)(a0 + ty * 4 + 2 * rp);
        __half2* d0 = (__half2*)(g_Yh + row0 * NCOLS + (c0 + tx * 4));
        d0[0] = __floats2half2_rn(lo[0], lo[1]);
        d0[1] = __floats2half2_rn(lo[2], lo[3]);

        __half2* d1 = (__half2*)(g_Yh + (row0 + 1) * NCOLS + (c0 + tx * 4));
        d1[0] = __floats2half2_rn(hi[0], hi[1]);
        d1[1] = __floats2half2_rn(hi[2], hi[3]);
    }
}

// ---------------------------------------------------------------------------
// Phase 2: half-warp per edge. Lane lid handles output features 4*lid..4*lid+3.
//   msg[i] = Yh[src][1024+i] + sum_k b_e[k] * Yh[src][k*64+i]
//   red.global.add.v4.f32 into out[dst]
// ---------------------------------------------------------------------------
__global__ void __launch_bounds__(256)
edge_kernel(const float* __restrict__ bond,
            const int* __restrict__ pair,
            float* __restrict__ out)
{
    const int warp = blockIdx.x * 8 + (threadIdx.x >> 5);
    const int half = (threadIdx.x >> 4) & 1;
    const int lid  = threadIdx.x & 15;
    const int e = warp * 2 + half;

    const int2 pr = ((const int2*)pair)[e];
    const int dst = pr.x;
    const int src = pr.y;

    const float4* __restrict__ bp = (const float4*)(bond + (size_t)e * 16);
    const float4 q0 = __ldg(bp + 0);
    const float4 q1 = __ldg(bp + 1);
    const float4 q2 = __ldg(bp + 2);
    const float4 q3 = __ldg(bp + 3);
    const float bk[16] = {q0.x, q0.y, q0.z, q0.w,
                          q1.x, q1.y, q1.z, q1.w,
                          q2.x, q2.y, q2.z, q2.w,
                          q3.x, q3.y, q3.z, q3.w};

    const __half* __restrict__ y = g_Yh + (size_t)src * NCOLS + 4 * lid;

    float m0, m1, m2, m3;
    {
        const uint2 v = *(const uint2*)(y + 1024);
        const float2 flo = __half22float2(*(const __half2*)&v.x);
        const float2 fhi = __half22float2(*(const __half2*)&v.y);
        m0 = flo.x; m1 = flo.y; m2 = fhi.x; m3 = fhi.y;
    }

    #pragma unroll
    for (int k = 0; k < 16; k++) {
        const uint2 v = *(const uint2*)(y + k * 64);
        const float2 flo = __half22float2(*(const __half2*)&v.x);
        const float2 fhi = __half22float2(*(const __half2*)&v.y);
        const float b = bk[k];
        m0 = fmaf(b, flo.x, m0);
        m1 = fmaf(b, flo.y, m1);
        m2 = fmaf(b, fhi.x, m2);
        m3 = fmaf(b, fhi.y, m3);
    }

    float* o = out + (size_t)dst * 64 + 4 * lid;   // 16B aligned
    asm volatile("red.global.add.v4.f32 [%0], {%1, %2, %3, %4};"
                 :: "l"(o), "f"(m0), "f"(m1), "f"(m2), "f"(m3)
                 : "memory");
}

extern "C" void kernel_launch(void* const* d_in, const int* in_sizes, int n_in,
                              void* d_out, int out_size)
{
    const float* atom = (const float*)d_in[0];      // [4480, 64]
    const float* bond = (const float*)d_in[1];      // [65536, 16]
    const int*   pair = (const int*)d_in[2];        // [65536, 2] int32
    const float* kern = (const float*)d_in[3];      // [16, 4096]
    const float* bias = (const float*)d_in[4];      // [4096]
    float*       out  = (float*)d_out;              // [4480, 64]

    (void)in_sizes; (void)n_in; (void)out_size;

    dim3 grid1(NUM_SEGMENTS / 64, NCOLS / 64);  // (70, 17); y==0 blocks zero `out`
    proj_kernel<<<grid1, 256>>>(atom, kern, bias, out);

    edge_kernel<<<N_EDGES / 16, 256>>>(bond, pair, out);
}